// round 2
// baseline (speedup 1.0000x reference)
#include <cuda_runtime.h>

// ---------------------------------------------------------------------------
// MultiHead_CrossAttention: B=4, L=4096, D=1024, H=16, hd=64
//   kv  = x @ Wkv + bkv          [16384, 2048]
//   q   = y @ Wq  + bq           [16384, 1024]
//   per position p: attn over HEADS axis (16x16), val[p] = softmax(q k^T/8) v
//   out = val @ Wo + bo          [16384, 1024]
// ---------------------------------------------------------------------------

#define M_ROWS 16384
#define DMODEL 1024
#define KV_COLS 2048

// scratch (cudaMalloc is forbidden; __device__ globals are the sanctioned path)
__device__ float g_kv [ (size_t)M_ROWS * KV_COLS ];   // 134 MB
__device__ float g_q  [ (size_t)M_ROWS * DMODEL  ];   // 67 MB
__device__ float g_val[ (size_t)M_ROWS * DMODEL  ];   // 67 MB

// ---------------------------------------------------------------------------
// SGEMM: C[M,N] = A[M,K] @ B[K,N] + bias[N]
// 128x128 tile, BK=8, 256 threads, 8x8 per thread (split 4+4 for vector LDS)
// ---------------------------------------------------------------------------
#define BM 128
#define BN 128
#define BK 8

__global__ __launch_bounds__(256, 2) void sgemm_bias_kernel(
    const float* __restrict__ A, const float* __restrict__ B,
    const float* __restrict__ bias, float* __restrict__ C,
    int M, int N, int K)
{
    __shared__ float As[BK][BM + 4];   // padded: conflict-free transposed stores
    __shared__ float Bs[BK][BN];

    const int tid  = threadIdx.x;
    const int brow = blockIdx.y * BM;
    const int bcol = blockIdx.x * BN;

    // global-load mapping
    const int a_row = tid >> 1;          // 0..127
    const int a_col = (tid & 1) * 4;     // 0 or 4
    const int b_row = tid >> 5;          // 0..7
    const int b_col = (tid & 31) * 4;    // 0..124

    // compute mapping: 16x16 thread grid, each thread covers rows
    // {ty*4..+3, 64+ty*4..+3} x cols {tx*4..+3, 64+tx*4..+3}
    const int tx = tid & 15;
    const int ty = tid >> 4;

    float acc[8][8];
#pragma unroll
    for (int i = 0; i < 8; i++)
#pragma unroll
        for (int j = 0; j < 8; j++) acc[i][j] = 0.f;

    const float* Aptr = A + (size_t)(brow + a_row) * K + a_col;
    const float* Bptr = B + (size_t)b_row * N + bcol + b_col;

    for (int k0 = 0; k0 < K; k0 += BK) {
        float4 av = *reinterpret_cast<const float4*>(Aptr + k0);
        float4 bv = *reinterpret_cast<const float4*>(Bptr + (size_t)k0 * N);
        As[a_col + 0][a_row] = av.x;
        As[a_col + 1][a_row] = av.y;
        As[a_col + 2][a_row] = av.z;
        As[a_col + 3][a_row] = av.w;
        *reinterpret_cast<float4*>(&Bs[b_row][b_col]) = bv;
        __syncthreads();

#pragma unroll
        for (int kk = 0; kk < BK; kk++) {
            float af[8], bf[8];
            float4 t;
            t = *reinterpret_cast<const float4*>(&As[kk][ty * 4]);
            af[0] = t.x; af[1] = t.y; af[2] = t.z; af[3] = t.w;
            t = *reinterpret_cast<const float4*>(&As[kk][64 + ty * 4]);
            af[4] = t.x; af[5] = t.y; af[6] = t.z; af[7] = t.w;
            t = *reinterpret_cast<const float4*>(&Bs[kk][tx * 4]);
            bf[0] = t.x; bf[1] = t.y; bf[2] = t.z; bf[3] = t.w;
            t = *reinterpret_cast<const float4*>(&Bs[kk][64 + tx * 4]);
            bf[4] = t.x; bf[5] = t.y; bf[6] = t.z; bf[7] = t.w;
#pragma unroll
            for (int i = 0; i < 8; i++)
#pragma unroll
                for (int j = 0; j < 8; j++)
                    acc[i][j] += af[i] * bf[j];
        }
        __syncthreads();
    }

    // epilogue: + bias, float4 stores
#pragma unroll
    for (int ii = 0; ii < 2; ii++) {
#pragma unroll
        for (int i = 0; i < 4; i++) {
            const int r = brow + ii * 64 + ty * 4 + i;
            float* Crow = C + (size_t)r * N + bcol;
#pragma unroll
            for (int jj = 0; jj < 2; jj++) {
                const int c = jj * 64 + tx * 4;
                float4 o;
                o.x = acc[ii * 4 + i][jj * 4 + 0] + bias[bcol + c + 0];
                o.y = acc[ii * 4 + i][jj * 4 + 1] + bias[bcol + c + 1];
                o.z = acc[ii * 4 + i][jj * 4 + 2] + bias[bcol + c + 2];
                o.w = acc[ii * 4 + i][jj * 4 + 3] + bias[bcol + c + 3];
                *reinterpret_cast<float4*>(Crow + c) = o;
            }
        }
    }
}

// ---------------------------------------------------------------------------
// Per-position head-axis attention.
// One block (256 threads) per position p in [0, 16384).
//   q row:  g_q[p*1024]  layout [H=16][64]
//   kv row: g_kv[p*2048] layout [H=16][128]  (k = [:,0:64], v = [:,64:128])
//   S[h][g] = (q_h . k_g) / 8 ; P = softmax_g(S) ; val[h] = sum_g P[h][g] v_g
// ---------------------------------------------------------------------------
#define KV_PAD 132   // padded row stride for skv (kills 16-way bank conflicts)

__global__ __launch_bounds__(256) void attn_kernel(
    const float* __restrict__ qbuf, const float* __restrict__ kvbuf,
    float* __restrict__ valbuf)
{
    __shared__ float sq[1024];
    __shared__ float skv[16 * KV_PAD];
    __shared__ float sP[16][16];

    const int p   = blockIdx.x;
    const int tid = threadIdx.x;

    // load q (1024 floats, linear)
    const float4* q4 = reinterpret_cast<const float4*>(qbuf + (size_t)p * 1024);
    reinterpret_cast<float4*>(sq)[tid] = q4[tid];

    // load kv (2048 floats) into padded layout [16][KV_PAD]
    const float4* kv4 = reinterpret_cast<const float4*>(kvbuf + (size_t)p * 2048);
#pragma unroll
    for (int r = 0; r < 2; r++) {
        int idx = tid + r * 256;          // float4 index in [0,512)
        int h   = idx >> 5;               // 32 float4 per kv row
        int c4  = idx & 31;
        float4 v = kv4[idx];
        *reinterpret_cast<float4*>(&skv[h * KV_PAD + c4 * 4]) = v;
    }
    __syncthreads();

    // S[h][g], one thread each
    {
        const int h = tid >> 4, g = tid & 15;
        const float* qr = sq  + h * 64;
        const float* kr = skv + g * KV_PAD;       // k half
        float s = 0.f;
#pragma unroll
        for (int d = 0; d < 64; d++) s += qr[d] * kr[d];
        sP[h][g] = s * 0.125f;
    }
    __syncthreads();

    // softmax over g, 16 threads
    if (tid < 16) {
        float m = -1e30f;
#pragma unroll
        for (int g = 0; g < 16; g++) m = fmaxf(m, sP[tid][g]);
        float e[16], sum = 0.f;
#pragma unroll
        for (int g = 0; g < 16; g++) { e[g] = __expf(sP[tid][g] - m); sum += e[g]; }
        const float inv = 1.f / sum;
#pragma unroll
        for (int g = 0; g < 16; g++) sP[tid][g] = e[g] * inv;
    }
    __syncthreads();

    // O[h][d0..d0+3], thread -> (h = tid/16, d0 = (tid%16)*4)
    {
        const int h  = tid >> 4;
        const int d0 = (tid & 15) * 4;
        float4 o = {0.f, 0.f, 0.f, 0.f};
#pragma unroll
        for (int g = 0; g < 16; g++) {
            const float pv = sP[h][g];
            const float4 vv = *reinterpret_cast<const float4*>(
                &skv[g * KV_PAD + 64 + d0]);     // v half
            o.x += pv * vv.x; o.y += pv * vv.y;
            o.z += pv * vv.z; o.w += pv * vv.w;
        }
        *reinterpret_cast<float4*>(valbuf + (size_t)p * 1024 + h * 64 + d0) = o;
    }
}

// ---------------------------------------------------------------------------

extern "C" void kernel_launch(void* const* d_in, const int* in_sizes, int n_in,
                              void* d_out, int out_size)
{
    const float* x   = (const float*)d_in[0];   // [4,4096,1024]
    const float* y   = (const float*)d_in[1];   // [4,4096,1024]
    const float* Wkv = (const float*)d_in[2];   // [1024,2048]
    const float* bkv = (const float*)d_in[3];   // [2048]
    const float* Wq  = (const float*)d_in[4];   // [1024,1024]
    const float* bq  = (const float*)d_in[5];   // [1024]
    const float* Wo  = (const float*)d_in[6];   // [1024,1024]
    const float* bo  = (const float*)d_in[7];   // [1024]
    float* out = (float*)d_out;                 // [4,4096,1024]

    float *kv_p, *q_p, *val_p;
    cudaGetSymbolAddress((void**)&kv_p,  g_kv);
    cudaGetSymbolAddress((void**)&q_p,   g_q);
    cudaGetSymbolAddress((void**)&val_p, g_val);

    // GEMM1: kv = x @ Wkv + bkv   [16384 x 2048 x 1024]
    {
        dim3 grid(KV_COLS / BN, M_ROWS / BM);
        sgemm_bias_kernel<<<grid, 256>>>(x, Wkv, bkv, kv_p,
                                         M_ROWS, KV_COLS, DMODEL);
    }
    // GEMM2: q = y @ Wq + bq      [16384 x 1024 x 1024]
    {
        dim3 grid(DMODEL / BN, M_ROWS / BM);
        sgemm_bias_kernel<<<grid, 256>>>(y, Wq, bq, q_p,
                                         M_ROWS, DMODEL, DMODEL);
    }
    // attention over heads axis, per position
    attn_kernel<<<M_ROWS, 256>>>(q_p, kv_p, val_p);

    // GEMM3: out = val @ Wo + bo  [16384 x 1024 x 1024]
    {
        dim3 grid(DMODEL / BN, M_ROWS / BM);
        sgemm_bias_kernel<<<grid, 256>>>(val_p, Wo, bo, out,
                                         M_ROWS, DMODEL, DMODEL);
    }
}

// round 4
// speedup vs baseline: 2.4926x; 2.4926x over previous
#include <cuda_runtime.h>
#include <cstdint>

// ---------------------------------------------------------------------------
// MultiHead_CrossAttention: B=4, L=4096, D=1024, H=16, hd=64
//   kv  = x @ Wkv + bkv      [16384, 2048]
//   q   = y @ Wq  + bq       [16384, 1024]
//   per-position head-axis attention (16x16 softmax)
//   out = val @ Wo + bo      [16384, 1024]
// GEMMs: tf32 mma.sync (m16n8k8) + ldmatrix + cp.async.
// (tcgen05 is unusable: harness emits compute_103 PTX, 'a'-features rejected.)
// ---------------------------------------------------------------------------

#define M_ROWS 16384
#define DMODEL 1024
#define KV_COLS 2048

__device__ float g_kv  [(size_t)M_ROWS * KV_COLS];
__device__ float g_q   [(size_t)M_ROWS * DMODEL];
__device__ float g_val [(size_t)M_ROWS * DMODEL];
__device__ float g_wkvT[(size_t)KV_COLS * DMODEL];
__device__ float g_wqT [(size_t)DMODEL * DMODEL];
__device__ float g_woT [(size_t)DMODEL * DMODEL];

__device__ __forceinline__ uint32_t smem_u32(const void* p) {
    uint32_t a;
    asm("{ .reg .u64 t; cvta.to.shared.u64 t, %1; cvt.u32.u64 %0, t; }"
        : "=r"(a) : "l"(p));
    return a;
}

__device__ __forceinline__ void cp_async16(uint32_t saddr, const void* gaddr) {
    asm volatile("cp.async.cg.shared.global [%0], [%1], 16;"
                 :: "r"(saddr), "l"(gaddr));
}
#define CP_COMMIT() asm volatile("cp.async.commit_group;" ::: "memory")
#define CP_WAIT(n)  asm volatile("cp.async.wait_group %0;" :: "n"(n) : "memory")

__device__ __forceinline__ uint32_t cvt_tf32(uint32_t x) {
    uint32_t r;
    asm("cvt.rna.tf32.f32 %0, %1;" : "=r"(r) : "r"(x));
    return r;
}

__device__ __forceinline__ void ldsm_x4(uint32_t& r0, uint32_t& r1,
                                        uint32_t& r2, uint32_t& r3, uint32_t a) {
    asm volatile("ldmatrix.sync.aligned.m8n8.x4.shared.b16 {%0,%1,%2,%3}, [%4];"
                 : "=r"(r0), "=r"(r1), "=r"(r2), "=r"(r3) : "r"(a));
}

__device__ __forceinline__ void mma_tf32(float* d, const uint32_t* a,
                                         uint32_t b0, uint32_t b1) {
    asm volatile(
        "mma.sync.aligned.m16n8k8.row.col.f32.tf32.tf32.f32 "
        "{%0,%1,%2,%3}, {%4,%5,%6,%7}, {%8,%9}, {%0,%1,%2,%3};"
        : "+f"(d[0]), "+f"(d[1]), "+f"(d[2]), "+f"(d[3])
        : "r"(a[0]), "r"(a[1]), "r"(a[2]), "r"(a[3]), "r"(b0), "r"(b1));
}

// ---------------------------------------------------------------------------
// GEMM: C[M,N] = A[M,K] @ BT[N,K]^T + bias
// 128x128 tile, BK=32, 4-stage cp.async ring, 8 warps x (64x32 warp tile)
// ---------------------------------------------------------------------------
#define BM 128
#define BN 128
#define BK 32
#define AP 36                              // padded row stride (floats)
#define TILE_FLOATS (128 * AP)             // 4608 floats = 18432 B
#define STAGE_FLOATS (2 * TILE_FLOATS)     // A + B
#define NSTAGE 4
#define GEMM_SMEM (NSTAGE * STAGE_FLOATS * 4)   // 147456 B

__global__ __launch_bounds__(256) void gemm_tf32_kernel(
    const float* __restrict__ A, const float* __restrict__ BT,
    const float* __restrict__ bias, float* __restrict__ C,
    int N, int K)
{
    extern __shared__ float smem[];
    const uint32_t sbase = smem_u32(smem);
    const int tid  = threadIdx.x;
    const int wid  = tid >> 5;
    const int lane = tid & 31;
    const int brow = blockIdx.y * BM;
    const int bcol = blockIdx.x * BN;

    const int wm = wid & 1;      // 2 m-groups of 64
    const int wn = wid >> 1;     // 4 n-groups of 32

    // ldmatrix per-lane address offsets (bytes), K-major rows of AP floats
    const int lr = lane & 7, lg = lane >> 3;
    const uint32_t a_lane = (uint32_t)(((lg & 1) * 8 + lr) * AP * 4 + (lg >> 1) * 16);
    const uint32_t b_lane = (uint32_t)(((lg >> 1) * 8 + lr) * AP * 4 + (lg & 1) * 16);

    float acc[4][4][4];
#pragma unroll
    for (int i = 0; i < 4; i++)
#pragma unroll
        for (int j = 0; j < 4; j++)
#pragma unroll
            for (int f = 0; f < 4; f++) acc[i][j][f] = 0.f;

    // per-thread global/shared mapping for cp.async (8 chunks of 16B / stage)
    const int NS = K / BK;   // 32

    auto issue = [&](int s) {
        const int k0 = s * BK;
        const uint32_t sa = sbase + (uint32_t)((s & (NSTAGE - 1)) * STAGE_FLOATS * 4);
        const uint32_t sb = sa + TILE_FLOATS * 4;
#pragma unroll
        for (int i = 0; i < 4; i++) {
            const int c = tid + i * 256;
            const int row = c >> 3, kc = (c & 7) * 4;
            cp_async16(sa + (uint32_t)((row * AP + kc) * 4),
                       A + (size_t)(brow + row) * K + k0 + kc);
        }
#pragma unroll
        for (int i = 0; i < 4; i++) {
            const int c = tid + i * 256;
            const int row = c >> 3, kc = (c & 7) * 4;
            cp_async16(sb + (uint32_t)((row * AP + kc) * 4),
                       BT + (size_t)(bcol + row) * K + k0 + kc);
        }
    };

    // prologue: stages 0..2
    issue(0); CP_COMMIT();
    issue(1); CP_COMMIT();
    issue(2); CP_COMMIT();

    for (int s = 0; s < NS; s++) {
        CP_WAIT(2);            // stage s resident
        __syncthreads();       // also: everyone done reading slot to be reused
        if (s + 3 < NS) issue(s + 3);
        CP_COMMIT();

        const uint32_t sa = sbase + (uint32_t)((s & (NSTAGE - 1)) * STAGE_FLOATS * 4);
        const uint32_t sb = sa + TILE_FLOATS * 4;
        const uint32_t aw = sa + a_lane + (uint32_t)(wm * 64 * AP * 4);
        const uint32_t bw = sb + b_lane + (uint32_t)(wn * 32 * AP * 4);

#pragma unroll
        for (int kk = 0; kk < 4; kk++) {           // 4 k8-steps
            uint32_t af[4][4];
#pragma unroll
            for (int mi = 0; mi < 4; mi++) {
                ldsm_x4(af[mi][0], af[mi][1], af[mi][2], af[mi][3],
                        aw + (uint32_t)(mi * 16 * AP * 4 + kk * 32));
#pragma unroll
                for (int f = 0; f < 4; f++) af[mi][f] = cvt_tf32(af[mi][f]);
            }
            uint32_t bf[2][4];
#pragma unroll
            for (int ni = 0; ni < 2; ni++) {
                ldsm_x4(bf[ni][0], bf[ni][1], bf[ni][2], bf[ni][3],
                        bw + (uint32_t)(ni * 16 * AP * 4 + kk * 32));
#pragma unroll
                for (int f = 0; f < 4; f++) bf[ni][f] = cvt_tf32(bf[ni][f]);
            }
#pragma unroll
            for (int mi = 0; mi < 4; mi++)
#pragma unroll
                for (int nj = 0; nj < 4; nj++)
                    mma_tf32(acc[mi][nj], af[mi],
                             bf[nj >> 1][(nj & 1) * 2], bf[nj >> 1][(nj & 1) * 2 + 1]);
        }
    }

    // epilogue: + bias, float2 stores
    const int lr4 = lane >> 2;
    const int lc2 = (lane & 3) * 2;
#pragma unroll
    for (int mi = 0; mi < 4; mi++) {
        const int r0 = brow + wm * 64 + mi * 16 + lr4;
#pragma unroll
        for (int nj = 0; nj < 4; nj++) {
            const int c = bcol + wn * 32 + nj * 8 + lc2;
            const float bx = bias[c], by = bias[c + 1];
            float2 v0 = {acc[mi][nj][0] + bx, acc[mi][nj][1] + by};
            float2 v1 = {acc[mi][nj][2] + bx, acc[mi][nj][3] + by};
            *reinterpret_cast<float2*>(C + (size_t)r0 * N + c) = v0;
            *reinterpret_cast<float2*>(C + (size_t)(r0 + 8) * N + c) = v1;
        }
    }
}

// ---------------------------------------------------------------------------
// Weight transpose: out[N,K] = in[K,N]
// ---------------------------------------------------------------------------
__global__ void transpose_kernel(const float* __restrict__ in, float* __restrict__ out,
                                 int R, int Ccols)
{
    __shared__ float t[32][33];
    const int c = blockIdx.x * 32 + threadIdx.x;
    const int r = blockIdx.y * 32 + threadIdx.y;
#pragma unroll
    for (int i = 0; i < 32; i += 8)
        t[threadIdx.y + i][threadIdx.x] = in[(size_t)(r + i) * Ccols + c];
    __syncthreads();
    const int oc   = blockIdx.y * 32 + threadIdx.x;
    const int orow = blockIdx.x * 32 + threadIdx.y;
#pragma unroll
    for (int i = 0; i < 32; i += 8)
        out[(size_t)(orow + i) * R + oc] = t[threadIdx.x][threadIdx.y + i];
}

// ---------------------------------------------------------------------------
// Per-position head-axis attention (unchanged; not the bottleneck)
// ---------------------------------------------------------------------------
#define KV_PAD 132

__global__ __launch_bounds__(256) void attn_kernel(
    const float* __restrict__ qbuf, const float* __restrict__ kvbuf,
    float* __restrict__ valbuf)
{
    __shared__ float sq[1024];
    __shared__ float skv[16 * KV_PAD];
    __shared__ float sP[16][16];

    const int p   = blockIdx.x;
    const int tid = threadIdx.x;

    const float4* q4 = reinterpret_cast<const float4*>(qbuf + (size_t)p * 1024);
    reinterpret_cast<float4*>(sq)[tid] = q4[tid];

    const float4* kv4 = reinterpret_cast<const float4*>(kvbuf + (size_t)p * 2048);
#pragma unroll
    for (int r = 0; r < 2; r++) {
        int idx = tid + r * 256;
        int h   = idx >> 5;
        int c4  = idx & 31;
        float4 v = kv4[idx];
        *reinterpret_cast<float4*>(&skv[h * KV_PAD + c4 * 4]) = v;
    }
    __syncthreads();

    {
        const int h = tid >> 4, g = tid & 15;
        const float* qr = sq  + h * 64;
        const float* kr = skv + g * KV_PAD;
        float s = 0.f;
#pragma unroll
        for (int d = 0; d < 64; d++) s += qr[d] * kr[d];
        sP[h][g] = s * 0.125f;
    }
    __syncthreads();

    if (tid < 16) {
        float m = -1e30f;
#pragma unroll
        for (int g = 0; g < 16; g++) m = fmaxf(m, sP[tid][g]);
        float e[16], sum = 0.f;
#pragma unroll
        for (int g = 0; g < 16; g++) { e[g] = __expf(sP[tid][g] - m); sum += e[g]; }
        const float inv = 1.f / sum;
#pragma unroll
        for (int g = 0; g < 16; g++) sP[tid][g] = e[g] * inv;
    }
    __syncthreads();

    {
        const int h  = tid >> 4;
        const int d0 = (tid & 15) * 4;
        float4 o = {0.f, 0.f, 0.f, 0.f};
#pragma unroll
        for (int g = 0; g < 16; g++) {
            const float pv = sP[h][g];
            const float4 vv = *reinterpret_cast<const float4*>(&skv[g * KV_PAD + 64 + d0]);
            o.x += pv * vv.x; o.y += pv * vv.y;
            o.z += pv * vv.z; o.w += pv * vv.w;
        }
        *reinterpret_cast<float4*>(valbuf + (size_t)p * 1024 + h * 64 + d0) = o;
    }
}

// ---------------------------------------------------------------------------

extern "C" void kernel_launch(void* const* d_in, const int* in_sizes, int n_in,
                              void* d_out, int out_size)
{
    const float* x   = (const float*)d_in[0];
    const float* y   = (const float*)d_in[1];
    const float* Wkv = (const float*)d_in[2];
    const float* bkv = (const float*)d_in[3];
    const float* Wq  = (const float*)d_in[4];
    const float* bq  = (const float*)d_in[5];
    const float* Wo  = (const float*)d_in[6];
    const float* bo  = (const float*)d_in[7];
    float* out = (float*)d_out;

    float *kv_p, *q_p, *val_p, *wkvT_p, *wqT_p, *woT_p;
    cudaGetSymbolAddress((void**)&kv_p,   g_kv);
    cudaGetSymbolAddress((void**)&q_p,    g_q);
    cudaGetSymbolAddress((void**)&val_p,  g_val);
    cudaGetSymbolAddress((void**)&wkvT_p, g_wkvT);
    cudaGetSymbolAddress((void**)&wqT_p,  g_wqT);
    cudaGetSymbolAddress((void**)&woT_p,  g_woT);

    cudaFuncSetAttribute(gemm_tf32_kernel,
                         cudaFuncAttributeMaxDynamicSharedMemorySize, GEMM_SMEM);

    // weight transposes: W[K,N] -> WT[N,K]
    transpose_kernel<<<dim3(KV_COLS / 32, DMODEL / 32), dim3(32, 8)>>>(Wkv, wkvT_p, DMODEL, KV_COLS);
    transpose_kernel<<<dim3(DMODEL / 32, DMODEL / 32), dim3(32, 8)>>>(Wq, wqT_p, DMODEL, DMODEL);
    transpose_kernel<<<dim3(DMODEL / 32, DMODEL / 32), dim3(32, 8)>>>(Wo, woT_p, DMODEL, DMODEL);

    // GEMM1: kv = x @ Wkv + bkv
    gemm_tf32_kernel<<<dim3(KV_COLS / BN, M_ROWS / BM), 256, GEMM_SMEM>>>(
        x, wkvT_p, bkv, kv_p, KV_COLS, DMODEL);
    // GEMM2: q = y @ Wq + bq
    gemm_tf32_kernel<<<dim3(DMODEL / BN, M_ROWS / BM), 256, GEMM_SMEM>>>(
        y, wqT_p, bq, q_p, DMODEL, DMODEL);
    // attention
    attn_kernel<<<M_ROWS, 256>>>(q_p, kv_p, val_p);
    // GEMM3: out = val @ Wo + bo
    gemm_tf32_kernel<<<dim3(DMODEL / BN, M_ROWS / BM), 256, GEMM_SMEM>>>(
        val_p, woT_p, bo, out, DMODEL, DMODEL);
}

// round 5
// speedup vs baseline: 3.0995x; 1.2435x over previous
#include <cuda_runtime.h>
#include <cstdint>

// ---------------------------------------------------------------------------
// MultiHead_CrossAttention: B=4, L=4096, D=1024, H=16, hd=64
//   kv  = x @ Wkv + bkv      [16384, 2048]
//   q   = y @ Wq  + bq       [16384, 1024]
//   per-position head-axis attention (16x16 softmax)
//   out = val @ Wo + bo      [16384, 1024]
// GEMMs: tf32 mma.sync (m16n8k8) + ldmatrix + cp.async, 3-stage ring,
// 2 CTAs/SM. Weights + val pre-rounded to tf32 so inner-loop cvt is A-only
// (and absent for GEMM3).
// ---------------------------------------------------------------------------

#define M_ROWS 16384
#define DMODEL 1024
#define KV_COLS 2048

__device__ float g_kv  [(size_t)M_ROWS * KV_COLS];
__device__ float g_q   [(size_t)M_ROWS * DMODEL];
__device__ float g_val [(size_t)M_ROWS * DMODEL];
__device__ float g_wkvT[(size_t)KV_COLS * DMODEL];
__device__ float g_wqT [(size_t)DMODEL * DMODEL];
__device__ float g_woT [(size_t)DMODEL * DMODEL];

__device__ __forceinline__ uint32_t smem_u32(const void* p) {
    uint32_t a;
    asm("{ .reg .u64 t; cvta.to.shared.u64 t, %1; cvt.u32.u64 %0, t; }"
        : "=r"(a) : "l"(p));
    return a;
}

__device__ __forceinline__ void cp_async16(uint32_t saddr, const void* gaddr) {
    asm volatile("cp.async.cg.shared.global [%0], [%1], 16;"
                 :: "r"(saddr), "l"(gaddr));
}
#define CP_COMMIT() asm volatile("cp.async.commit_group;" ::: "memory")
#define CP_WAIT(n)  asm volatile("cp.async.wait_group %0;" :: "n"(n) : "memory")

__device__ __forceinline__ uint32_t cvt_tf32(uint32_t x) {
    uint32_t r;
    asm("cvt.rna.tf32.f32 %0, %1;" : "=r"(r) : "r"(x));
    return r;
}
__device__ __forceinline__ float to_tf32f(float x) {
    float r;
    asm("cvt.rna.tf32.f32 %0, %1;" : "=f"(r) : "f"(x));
    return r;
}

__device__ __forceinline__ void ldsm_x4(uint32_t& r0, uint32_t& r1,
                                        uint32_t& r2, uint32_t& r3, uint32_t a) {
    asm volatile("ldmatrix.sync.aligned.m8n8.x4.shared.b16 {%0,%1,%2,%3}, [%4];"
                 : "=r"(r0), "=r"(r1), "=r"(r2), "=r"(r3) : "r"(a));
}

__device__ __forceinline__ void mma_tf32(float* d, const uint32_t* a,
                                         uint32_t b0, uint32_t b1) {
    asm volatile(
        "mma.sync.aligned.m16n8k8.row.col.f32.tf32.tf32.f32 "
        "{%0,%1,%2,%3}, {%4,%5,%6,%7}, {%8,%9}, {%0,%1,%2,%3};"
        : "+f"(d[0]), "+f"(d[1]), "+f"(d[2]), "+f"(d[3])
        : "r"(a[0]), "r"(a[1]), "r"(a[2]), "r"(a[3]), "r"(b0), "r"(b1));
}

// ---------------------------------------------------------------------------
// GEMM: C[M,N] = A[M,K] @ BT[N,K]^T + bias
// 128x128 tile, BK=32, 3-stage cp.async ring, 8 warps x (64x32 warp tile)
// BT (and, when !CVT_A, A) must be pre-rounded to tf32.
// ---------------------------------------------------------------------------
#define BM 128
#define BN 128
#define BK 32
#define AP 36                              // padded row stride (floats)
#define TILE_FLOATS (128 * AP)             // 4608 floats = 18432 B
#define STAGE_FLOATS (2 * TILE_FLOATS)     // A + B
#define STAGE_BYTES (STAGE_FLOATS * 4)     // 36864
#define NSTAGE 3
#define GEMM_SMEM (NSTAGE * STAGE_BYTES)   // 110592 B -> 2 CTAs/SM

template <bool CVT_A>
__global__ __launch_bounds__(256, 2) void gemm_tf32_kernel(
    const float* __restrict__ A, const float* __restrict__ BT,
    const float* __restrict__ bias, float* __restrict__ C,
    int N, int K)
{
    extern __shared__ float smem[];
    const uint32_t sbase = smem_u32(smem);
    const int tid  = threadIdx.x;
    const int wid  = tid >> 5;
    const int lane = tid & 31;
    const int brow = blockIdx.y * BM;
    const int bcol = blockIdx.x * BN;

    const int wm = wid & 1;      // 2 m-groups of 64
    const int wn = wid >> 1;     // 4 n-groups of 32

    // ldmatrix per-lane address offsets (bytes), K-major rows of AP floats
    const int lr = lane & 7, lg = lane >> 3;
    const uint32_t a_lane = (uint32_t)(((lg & 1) * 8 + lr) * AP * 4 + (lg >> 1) * 16);
    const uint32_t b_lane = (uint32_t)(((lg >> 1) * 8 + lr) * AP * 4 + (lg & 1) * 16);

    float acc[4][4][4];
#pragma unroll
    for (int i = 0; i < 4; i++)
#pragma unroll
        for (int j = 0; j < 4; j++)
#pragma unroll
            for (int f = 0; f < 4; f++) acc[i][j][f] = 0.f;

    const int NS = K / BK;   // 32

    auto issue = [&](int s, int slot) {
        const int k0 = s * BK;
        const uint32_t sa = sbase + (uint32_t)(slot * STAGE_BYTES);
        const uint32_t sb = sa + TILE_FLOATS * 4;
#pragma unroll
        for (int i = 0; i < 4; i++) {
            const int c = tid + i * 256;
            const int row = c >> 3, kc = (c & 7) * 4;
            cp_async16(sa + (uint32_t)((row * AP + kc) * 4),
                       A + (size_t)(brow + row) * K + k0 + kc);
        }
#pragma unroll
        for (int i = 0; i < 4; i++) {
            const int c = tid + i * 256;
            const int row = c >> 3, kc = (c & 7) * 4;
            cp_async16(sb + (uint32_t)((row * AP + kc) * 4),
                       BT + (size_t)(bcol + row) * K + k0 + kc);
        }
    };

    // prologue: stages 0,1
    issue(0, 0); CP_COMMIT();
    issue(1, 1); CP_COMMIT();

    int slot = 0, nslot = 2;   // slot of stage s; slot for stage s+2
    for (int s = 0; s < NS; s++) {
        CP_WAIT(1);            // stage s resident (<=1 group pending)
        __syncthreads();       // all warps done reading slot `nslot` (stage s-1's... s+2's target)
        if (s + 2 < NS) issue(s + 2, nslot);
        CP_COMMIT();

        const uint32_t sa = sbase + (uint32_t)(slot * STAGE_BYTES);
        const uint32_t sb = sa + TILE_FLOATS * 4;
        const uint32_t aw = sa + a_lane + (uint32_t)(wm * 64 * AP * 4);
        const uint32_t bw = sb + b_lane + (uint32_t)(wn * 32 * AP * 4);

#pragma unroll
        for (int kk = 0; kk < 4; kk++) {           // 4 k8-steps
            uint32_t af[4][4];
#pragma unroll
            for (int mi = 0; mi < 4; mi++) {
                ldsm_x4(af[mi][0], af[mi][1], af[mi][2], af[mi][3],
                        aw + (uint32_t)(mi * 16 * AP * 4 + kk * 32));
                if (CVT_A) {
#pragma unroll
                    for (int f = 0; f < 4; f++) af[mi][f] = cvt_tf32(af[mi][f]);
                }
            }
            uint32_t bf[2][4];
#pragma unroll
            for (int ni = 0; ni < 2; ni++) {
                ldsm_x4(bf[ni][0], bf[ni][1], bf[ni][2], bf[ni][3],
                        bw + (uint32_t)(ni * 16 * AP * 4 + kk * 32));
            }
#pragma unroll
            for (int mi = 0; mi < 4; mi++)
#pragma unroll
                for (int nj = 0; nj < 4; nj++)
                    mma_tf32(acc[mi][nj], af[mi],
                             bf[nj >> 1][(nj & 1) * 2], bf[nj >> 1][(nj & 1) * 2 + 1]);
        }

        slot = (slot == NSTAGE - 1) ? 0 : slot + 1;
        nslot = (nslot == NSTAGE - 1) ? 0 : nslot + 1;
    }

    // epilogue: + bias, float2 stores
    const int lr4 = lane >> 2;
    const int lc2 = (lane & 3) * 2;
#pragma unroll
    for (int mi = 0; mi < 4; mi++) {
        const int r0 = brow + wm * 64 + mi * 16 + lr4;
#pragma unroll
        for (int nj = 0; nj < 4; nj++) {
            const int c = bcol + wn * 32 + nj * 8 + lc2;
            const float bx = bias[c], by = bias[c + 1];
            float2 v0 = {acc[mi][nj][0] + bx, acc[mi][nj][1] + by};
            float2 v1 = {acc[mi][nj][2] + bx, acc[mi][nj][3] + by};
            *reinterpret_cast<float2*>(C + (size_t)r0 * N + c) = v0;
            *reinterpret_cast<float2*>(C + (size_t)(r0 + 8) * N + c) = v1;
        }
    }
}

// ---------------------------------------------------------------------------
// Weight transpose + tf32 pre-round: out[N,K] = tf32(in[K,N])
// ---------------------------------------------------------------------------
__global__ void transpose_kernel(const float* __restrict__ in, float* __restrict__ out,
                                 int R, int Ccols)
{
    __shared__ float t[32][33];
    const int c = blockIdx.x * 32 + threadIdx.x;
    const int r = blockIdx.y * 32 + threadIdx.y;
#pragma unroll
    for (int i = 0; i < 32; i += 8)
        t[threadIdx.y + i][threadIdx.x] = in[(size_t)(r + i) * Ccols + c];
    __syncthreads();
    const int oc   = blockIdx.y * 32 + threadIdx.x;
    const int orow = blockIdx.x * 32 + threadIdx.y;
#pragma unroll
    for (int i = 0; i < 32; i += 8)
        out[(size_t)(orow + i) * R + oc] = to_tf32f(t[threadIdx.x][threadIdx.y + i]);
}

// ---------------------------------------------------------------------------
// Per-position head-axis attention; val output pre-rounded to tf32 for GEMM3.
// ---------------------------------------------------------------------------
#define KV_PAD 132

__global__ __launch_bounds__(256) void attn_kernel(
    const float* __restrict__ qbuf, const float* __restrict__ kvbuf,
    float* __restrict__ valbuf)
{
    __shared__ float sq[1024];
    __shared__ float skv[16 * KV_PAD];
    __shared__ float sP[16][16];

    const int p   = blockIdx.x;
    const int tid = threadIdx.x;

    const float4* q4 = reinterpret_cast<const float4*>(qbuf + (size_t)p * 1024);
    reinterpret_cast<float4*>(sq)[tid] = q4[tid];

    const float4* kv4 = reinterpret_cast<const float4*>(kvbuf + (size_t)p * 2048);
#pragma unroll
    for (int r = 0; r < 2; r++) {
        int idx = tid + r * 256;
        int h   = idx >> 5;
        int c4  = idx & 31;
        float4 v = kv4[idx];
        *reinterpret_cast<float4*>(&skv[h * KV_PAD + c4 * 4]) = v;
    }
    __syncthreads();

    {
        const int h = tid >> 4, g = tid & 15;
        const float* qr = sq  + h * 64;
        const float* kr = skv + g * KV_PAD;
        float s = 0.f;
#pragma unroll
        for (int d = 0; d < 64; d++) s += qr[d] * kr[d];
        sP[h][g] = s * 0.125f;
    }
    __syncthreads();

    if (tid < 16) {
        float m = -1e30f;
#pragma unroll
        for (int g = 0; g < 16; g++) m = fmaxf(m, sP[tid][g]);
        float e[16], sum = 0.f;
#pragma unroll
        for (int g = 0; g < 16; g++) { e[g] = __expf(sP[tid][g] - m); sum += e[g]; }
        const float inv = 1.f / sum;
#pragma unroll
        for (int g = 0; g < 16; g++) sP[tid][g] = e[g] * inv;
    }
    __syncthreads();

    {
        const int h  = tid >> 4;
        const int d0 = (tid & 15) * 4;
        float4 o = {0.f, 0.f, 0.f, 0.f};
#pragma unroll
        for (int g = 0; g < 16; g++) {
            const float pv = sP[h][g];
            const float4 vv = *reinterpret_cast<const float4*>(&skv[g * KV_PAD + 64 + d0]);
            o.x += pv * vv.x; o.y += pv * vv.y;
            o.z += pv * vv.z; o.w += pv * vv.w;
        }
        o.x = to_tf32f(o.x); o.y = to_tf32f(o.y);
        o.z = to_tf32f(o.z); o.w = to_tf32f(o.w);
        *reinterpret_cast<float4*>(valbuf + (size_t)p * 1024 + h * 64 + d0) = o;
    }
}

// ---------------------------------------------------------------------------

extern "C" void kernel_launch(void* const* d_in, const int* in_sizes, int n_in,
                              void* d_out, int out_size)
{
    const float* x   = (const float*)d_in[0];
    const float* y   = (const float*)d_in[1];
    const float* Wkv = (const float*)d_in[2];
    const float* bkv = (const float*)d_in[3];
    const float* Wq  = (const float*)d_in[4];
    const float* bq  = (const float*)d_in[5];
    const float* Wo  = (const float*)d_in[6];
    const float* bo  = (const float*)d_in[7];
    float* out = (float*)d_out;

    float *kv_p, *q_p, *val_p, *wkvT_p, *wqT_p, *woT_p;
    cudaGetSymbolAddress((void**)&kv_p,   g_kv);
    cudaGetSymbolAddress((void**)&q_p,    g_q);
    cudaGetSymbolAddress((void**)&val_p,  g_val);
    cudaGetSymbolAddress((void**)&wkvT_p, g_wkvT);
    cudaGetSymbolAddress((void**)&wqT_p,  g_wqT);
    cudaGetSymbolAddress((void**)&woT_p,  g_woT);

    cudaFuncSetAttribute(gemm_tf32_kernel<true>,
                         cudaFuncAttributeMaxDynamicSharedMemorySize, GEMM_SMEM);
    cudaFuncSetAttribute(gemm_tf32_kernel<false>,
                         cudaFuncAttributeMaxDynamicSharedMemorySize, GEMM_SMEM);

    // weight transposes + tf32 pre-round: W[K,N] -> WT[N,K]
    transpose_kernel<<<dim3(KV_COLS / 32, DMODEL / 32), dim3(32, 8)>>>(Wkv, wkvT_p, DMODEL, KV_COLS);
    transpose_kernel<<<dim3(DMODEL / 32, DMODEL / 32), dim3(32, 8)>>>(Wq, wqT_p, DMODEL, DMODEL);
    transpose_kernel<<<dim3(DMODEL / 32, DMODEL / 32), dim3(32, 8)>>>(Wo, woT_p, DMODEL, DMODEL);

    // GEMM1: kv = x @ Wkv + bkv
    gemm_tf32_kernel<true><<<dim3(KV_COLS / BN, M_ROWS / BM), 256, GEMM_SMEM>>>(
        x, wkvT_p, bkv, kv_p, KV_COLS, DMODEL);
    // GEMM2: q = y @ Wq + bq
    gemm_tf32_kernel<true><<<dim3(DMODEL / BN, M_ROWS / BM), 256, GEMM_SMEM>>>(
        y, wqT_p, bq, q_p, DMODEL, DMODEL);
    // attention
    attn_kernel<<<M_ROWS, 256>>>(q_p, kv_p, val_p);
    // GEMM3: out = val @ Wo + bo  (val pre-rounded -> no in-loop cvt)
    gemm_tf32_kernel<false><<<dim3(DMODEL / BN, M_ROWS / BM), 256, GEMM_SMEM>>>(
        val_p, woT_p, bo, out, DMODEL, DMODEL);
}

// round 6
// speedup vs baseline: 4.7945x; 1.5469x over previous
#include <cuda_runtime.h>
#include <cuda_fp16.h>
#include <cstdint>

// ---------------------------------------------------------------------------
// MultiHead_CrossAttention: B=4, L=4096, D=1024, H=16, hd=64
//   kv  = x @ Wkv + bkv      [16384, 2048]
//   q   = y @ Wq  + bq       [16384, 1024]
//   per-position head-axis attention (16x16 softmax)
//   out = val @ Wo + bo      [16384, 1024]
// GEMMs: fp16 mma.sync m16n8k16 (fp32 accum), ldmatrix b16, cp.async,
// 3-stage ring, 2 CTAs/SM. All GEMM operands pre-converted to fp16
// (fp16 mantissa == tf32 mantissa -> same ~5e-4 rel err, 2x MAC rate).
// ---------------------------------------------------------------------------

#define M_ROWS 16384
#define DMODEL 1024
#define KV_COLS 2048

__device__ float  g_kv  [(size_t)M_ROWS * KV_COLS];   // fp32 (attn input)
__device__ float  g_q   [(size_t)M_ROWS * DMODEL];    // fp32 (attn input)
__device__ __half g_xh  [(size_t)M_ROWS * DMODEL];
__device__ __half g_yh  [(size_t)M_ROWS * DMODEL];
__device__ __half g_valh[(size_t)M_ROWS * DMODEL];
__device__ __half g_wkvT[(size_t)KV_COLS * DMODEL];
__device__ __half g_wqT [(size_t)DMODEL * DMODEL];
__device__ __half g_woT [(size_t)DMODEL * DMODEL];

__device__ __forceinline__ uint32_t smem_u32(const void* p) {
    uint32_t a;
    asm("{ .reg .u64 t; cvta.to.shared.u64 t, %1; cvt.u32.u64 %0, t; }"
        : "=r"(a) : "l"(p));
    return a;
}

__device__ __forceinline__ void cp_async16(uint32_t saddr, const void* gaddr) {
    asm volatile("cp.async.cg.shared.global [%0], [%1], 16;"
                 :: "r"(saddr), "l"(gaddr));
}
#define CP_COMMIT() asm volatile("cp.async.commit_group;" ::: "memory")
#define CP_WAIT(n)  asm volatile("cp.async.wait_group %0;" :: "n"(n) : "memory")

__device__ __forceinline__ void ldsm_x4(uint32_t& r0, uint32_t& r1,
                                        uint32_t& r2, uint32_t& r3, uint32_t a) {
    asm volatile("ldmatrix.sync.aligned.m8n8.x4.shared.b16 {%0,%1,%2,%3}, [%4];"
                 : "=r"(r0), "=r"(r1), "=r"(r2), "=r"(r3) : "r"(a));
}

__device__ __forceinline__ void mma_f16(float* d, const uint32_t* a,
                                        uint32_t b0, uint32_t b1) {
    asm volatile(
        "mma.sync.aligned.m16n8k16.row.col.f32.f16.f16.f32 "
        "{%0,%1,%2,%3}, {%4,%5,%6,%7}, {%8,%9}, {%0,%1,%2,%3};"
        : "+f"(d[0]), "+f"(d[1]), "+f"(d[2]), "+f"(d[3])
        : "r"(a[0]), "r"(a[1]), "r"(a[2]), "r"(a[3]), "r"(b0), "r"(b1));
}

// ---------------------------------------------------------------------------
// GEMM: C[M,N](fp32) = Ah[M,K](fp16) @ BTh[N,K](fp16)^T + bias
// 128x128 tile, BK=64, 3-stage cp.async ring, 8 warps x (64x32 warp tile)
// ---------------------------------------------------------------------------
#define BM 128
#define BN 128
#define BK 64
#define APH 72                              // halves per smem row (64 + 8 pad)
#define ROWB (APH * 2)                      // 144 B row stride
#define TILE_BYTES (128 * ROWB)             // 18432
#define STAGE_BYTES (2 * TILE_BYTES)        // 36864
#define NSTAGE 3
#define GEMM_SMEM (NSTAGE * STAGE_BYTES)    // 110592 B -> 2 CTAs/SM

__global__ __launch_bounds__(256, 2) void gemm_f16_kernel(
    const __half* __restrict__ A, const __half* __restrict__ BT,
    const float* __restrict__ bias, float* __restrict__ C,
    int N, int K)
{
    extern __shared__ char smem[];
    const uint32_t sbase = smem_u32(smem);
    const int tid  = threadIdx.x;
    const int wid  = tid >> 5;
    const int lane = tid & 31;
    const int brow = blockIdx.y * BM;
    const int bcol = blockIdx.x * BN;

    const int wm = wid & 1;      // 2 m-groups of 64
    const int wn = wid >> 1;     // 4 n-groups of 32

    // ldmatrix lane address (bytes): matrices ordered (rowblk = lg&1, kblk = lg>>1)
    const int lr = lane & 7, lg = lane >> 3;
    const uint32_t frag_lane = (uint32_t)(((lg & 1) * 8 + lr) * ROWB + (lg >> 1) * 16);

    float acc[4][4][4];
#pragma unroll
    for (int i = 0; i < 4; i++)
#pragma unroll
        for (int j = 0; j < 4; j++)
#pragma unroll
            for (int f = 0; f < 4; f++) acc[i][j][f] = 0.f;

    const int NS = K / BK;   // 16

    // 1024 16B-chunks per tile, 4 per thread per tile (row = 8 chunks of 16B)
    auto issue = [&](int s, int slot) {
        const int k0 = s * BK;
        const uint32_t sa = sbase + (uint32_t)(slot * STAGE_BYTES);
        const uint32_t sb = sa + TILE_BYTES;
#pragma unroll
        for (int i = 0; i < 4; i++) {
            const int c = tid + i * 256;
            const int row = c >> 3, kc = c & 7;
            cp_async16(sa + (uint32_t)(row * ROWB + kc * 16),
                       A + (size_t)(brow + row) * K + k0 + kc * 8);
        }
#pragma unroll
        for (int i = 0; i < 4; i++) {
            const int c = tid + i * 256;
            const int row = c >> 3, kc = c & 7;
            cp_async16(sb + (uint32_t)(row * ROWB + kc * 16),
                       BT + (size_t)(bcol + row) * K + k0 + kc * 8);
        }
    };

    issue(0, 0); CP_COMMIT();
    issue(1, 1); CP_COMMIT();

    int slot = 0, nslot = 2;
    for (int s = 0; s < NS; s++) {
        CP_WAIT(1);
        __syncthreads();
        if (s + 2 < NS) issue(s + 2, nslot);
        CP_COMMIT();

        const uint32_t sa = sbase + (uint32_t)(slot * STAGE_BYTES);
        const uint32_t sb = sa + TILE_BYTES;
        const uint32_t aw = sa + frag_lane + (uint32_t)(wm * 64 * ROWB);
        const uint32_t bw = sb + frag_lane + (uint32_t)(wn * 32 * ROWB);

#pragma unroll
        for (int kk = 0; kk < 4; kk++) {           // 4 k16-steps (32 B each)
            uint32_t af[4][4];
#pragma unroll
            for (int mi = 0; mi < 4; mi++)
                ldsm_x4(af[mi][0], af[mi][1], af[mi][2], af[mi][3],
                        aw + (uint32_t)(mi * 16 * ROWB + kk * 32));
            uint32_t bf[2][4];
#pragma unroll
            for (int ni = 0; ni < 2; ni++)
                ldsm_x4(bf[ni][0], bf[ni][1], bf[ni][2], bf[ni][3],
                        bw + (uint32_t)(ni * 16 * ROWB + kk * 32));
#pragma unroll
            for (int mi = 0; mi < 4; mi++)
#pragma unroll
                for (int nj = 0; nj < 4; nj++)
                    mma_f16(acc[mi][nj], af[mi],
                            bf[nj >> 1][nj & 1], bf[nj >> 1][(nj & 1) + 2]);
        }

        slot = (slot == NSTAGE - 1) ? 0 : slot + 1;
        nslot = (nslot == NSTAGE - 1) ? 0 : nslot + 1;
    }

    // epilogue: + bias, float2 stores (m16n8 D fragment layout)
    const int lr4 = lane >> 2;
    const int lc2 = (lane & 3) * 2;
#pragma unroll
    for (int mi = 0; mi < 4; mi++) {
        const int r0 = brow + wm * 64 + mi * 16 + lr4;
#pragma unroll
        for (int nj = 0; nj < 4; nj++) {
            const int c = bcol + wn * 32 + nj * 8 + lc2;
            const float bx = bias[c], by = bias[c + 1];
            float2 v0 = {acc[mi][nj][0] + bx, acc[mi][nj][1] + by};
            float2 v1 = {acc[mi][nj][2] + bx, acc[mi][nj][3] + by};
            *reinterpret_cast<float2*>(C + (size_t)r0 * N + c) = v0;
            *reinterpret_cast<float2*>(C + (size_t)(r0 + 8) * N + c) = v1;
        }
    }
}

// ---------------------------------------------------------------------------
// fp32 -> fp16 bulk convert (8 elems/thread)
// ---------------------------------------------------------------------------
__global__ void cvt_f16_kernel(const float* __restrict__ in, __half* __restrict__ out)
{
    const size_t i = (size_t)(blockIdx.x * blockDim.x + threadIdx.x) * 8;
    float4 a = *reinterpret_cast<const float4*>(in + i);
    float4 b = *reinterpret_cast<const float4*>(in + i + 4);
    __half2 h[4];
    h[0] = __floats2half2_rn(a.x, a.y);
    h[1] = __floats2half2_rn(a.z, a.w);
    h[2] = __floats2half2_rn(b.x, b.y);
    h[3] = __floats2half2_rn(b.z, b.w);
    *reinterpret_cast<uint4*>(out + i) = *reinterpret_cast<uint4*>(h);
}

// ---------------------------------------------------------------------------
// Weight transpose + fp16 convert: out[N,K](half) = in[K,N](fp32)
// ---------------------------------------------------------------------------
__global__ void transpose_h_kernel(const float* __restrict__ in, __half* __restrict__ out,
                                   int R, int Ccols)
{
    __shared__ float t[32][33];
    const int c = blockIdx.x * 32 + threadIdx.x;
    const int r = blockIdx.y * 32 + threadIdx.y;
#pragma unroll
    for (int i = 0; i < 32; i += 8)
        t[threadIdx.y + i][threadIdx.x] = in[(size_t)(r + i) * Ccols + c];
    __syncthreads();
    const int oc   = blockIdx.y * 32 + threadIdx.x;
    const int orow = blockIdx.x * 32 + threadIdx.y;
#pragma unroll
    for (int i = 0; i < 32; i += 8)
        out[(size_t)(orow + i) * R + oc] = __float2half_rn(t[threadIdx.x][threadIdx.y + i]);
}

// ---------------------------------------------------------------------------
// Per-position head-axis attention; writes val as fp16 for GEMM3.
// ---------------------------------------------------------------------------
#define KV_PAD 132

__global__ __launch_bounds__(256) void attn_kernel(
    const float* __restrict__ qbuf, const float* __restrict__ kvbuf,
    __half* __restrict__ valbuf)
{
    __shared__ float sq[1024];
    __shared__ float skv[16 * KV_PAD];
    __shared__ float sP[16][16];

    const int p   = blockIdx.x;
    const int tid = threadIdx.x;

    const float4* q4 = reinterpret_cast<const float4*>(qbuf + (size_t)p * 1024);
    reinterpret_cast<float4*>(sq)[tid] = q4[tid];

    const float4* kv4 = reinterpret_cast<const float4*>(kvbuf + (size_t)p * 2048);
#pragma unroll
    for (int r = 0; r < 2; r++) {
        int idx = tid + r * 256;
        int h   = idx >> 5;
        int c4  = idx & 31;
        float4 v = kv4[idx];
        *reinterpret_cast<float4*>(&skv[h * KV_PAD + c4 * 4]) = v;
    }
    __syncthreads();

    {
        const int h = tid >> 4, g = tid & 15;
        const float* qr = sq  + h * 64;
        const float* kr = skv + g * KV_PAD;
        float s = 0.f;
#pragma unroll
        for (int d = 0; d < 64; d++) s += qr[d] * kr[d];
        sP[h][g] = s * 0.125f;
    }
    __syncthreads();

    if (tid < 16) {
        float m = -1e30f;
#pragma unroll
        for (int g = 0; g < 16; g++) m = fmaxf(m, sP[tid][g]);
        float e[16], sum = 0.f;
#pragma unroll
        for (int g = 0; g < 16; g++) { e[g] = __expf(sP[tid][g] - m); sum += e[g]; }
        const float inv = 1.f / sum;
#pragma unroll
        for (int g = 0; g < 16; g++) sP[tid][g] = e[g] * inv;
    }
    __syncthreads();

    {
        const int h  = tid >> 4;
        const int d0 = (tid & 15) * 4;
        float4 o = {0.f, 0.f, 0.f, 0.f};
#pragma unroll
        for (int g = 0; g < 16; g++) {
            const float pv = sP[h][g];
            const float4 vv = *reinterpret_cast<const float4*>(&skv[g * KV_PAD + 64 + d0]);
            o.x += pv * vv.x; o.y += pv * vv.y;
            o.z += pv * vv.z; o.w += pv * vv.w;
        }
        __half2 h01 = __floats2half2_rn(o.x, o.y);
        __half2 h23 = __floats2half2_rn(o.z, o.w);
        uint2 pk = {*reinterpret_cast<uint32_t*>(&h01), *reinterpret_cast<uint32_t*>(&h23)};
        *reinterpret_cast<uint2*>(valbuf + (size_t)p * 1024 + h * 64 + d0) = pk;
    }
}

// ---------------------------------------------------------------------------

extern "C" void kernel_launch(void* const* d_in, const int* in_sizes, int n_in,
                              void* d_out, int out_size)
{
    const float* x   = (const float*)d_in[0];
    const float* y   = (const float*)d_in[1];
    const float* Wkv = (const float*)d_in[2];
    const float* bkv = (const float*)d_in[3];
    const float* Wq  = (const float*)d_in[4];
    const float* bq  = (const float*)d_in[5];
    const float* Wo  = (const float*)d_in[6];
    const float* bo  = (const float*)d_in[7];
    float* out = (float*)d_out;

    float *kv_p, *q_p;
    __half *xh_p, *yh_p, *valh_p, *wkvT_p, *wqT_p, *woT_p;
    cudaGetSymbolAddress((void**)&kv_p,   g_kv);
    cudaGetSymbolAddress((void**)&q_p,    g_q);
    cudaGetSymbolAddress((void**)&xh_p,   g_xh);
    cudaGetSymbolAddress((void**)&yh_p,   g_yh);
    cudaGetSymbolAddress((void**)&valh_p, g_valh);
    cudaGetSymbolAddress((void**)&wkvT_p, g_wkvT);
    cudaGetSymbolAddress((void**)&wqT_p,  g_wqT);
    cudaGetSymbolAddress((void**)&woT_p,  g_woT);

    cudaFuncSetAttribute(gemm_f16_kernel,
                         cudaFuncAttributeMaxDynamicSharedMemorySize, GEMM_SMEM);

    // input converts + weight transposes (all independent, small)
    const int cvt_blocks = (M_ROWS * DMODEL) / (256 * 8);
    cvt_f16_kernel<<<cvt_blocks, 256>>>(x, xh_p);
    cvt_f16_kernel<<<cvt_blocks, 256>>>(y, yh_p);
    transpose_h_kernel<<<dim3(KV_COLS / 32, DMODEL / 32), dim3(32, 8)>>>(Wkv, wkvT_p, DMODEL, KV_COLS);
    transpose_h_kernel<<<dim3(DMODEL / 32, DMODEL / 32), dim3(32, 8)>>>(Wq, wqT_p, DMODEL, DMODEL);
    transpose_h_kernel<<<dim3(DMODEL / 32, DMODEL / 32), dim3(32, 8)>>>(Wo, woT_p, DMODEL, DMODEL);

    // GEMM1: kv = x @ Wkv + bkv
    gemm_f16_kernel<<<dim3(KV_COLS / BN, M_ROWS / BM), 256, GEMM_SMEM>>>(
        xh_p, wkvT_p, bkv, kv_p, KV_COLS, DMODEL);
    // GEMM2: q = y @ Wq + bq
    gemm_f16_kernel<<<dim3(DMODEL / BN, M_ROWS / BM), 256, GEMM_SMEM>>>(
        yh_p, wqT_p, bq, q_p, DMODEL, DMODEL);
    // attention (fp32 in, fp16 val out)
    attn_kernel<<<M_ROWS, 256>>>(q_p, kv_p, valh_p);
    // GEMM3: out = val @ Wo + bo
    gemm_f16_kernel<<<dim3(DMODEL / BN, M_ROWS / BM), 256, GEMM_SMEM>>>(
        valh_p, woT_p, bo, out, DMODEL, DMODEL);
}

// round 7
// speedup vs baseline: 4.8560x; 1.0128x over previous
#include <cuda_runtime.h>
#include <cuda_fp16.h>
#include <cstdint>

// ---------------------------------------------------------------------------
// MultiHead_CrossAttention: B=4, L=4096, D=1024, H=16, hd=64
//   kv  = x @ Wkv + bkv      [16384, 2048]  (fp16 staged)
//   q   = y @ Wq  + bq       [16384, 1024]  (fp16 staged)
//   per-position head-axis attention (16x16 softmax, fp32 math)
//   out = val @ Wo + bo      [16384, 1024]  (fp32)
// GEMMs: fp16 mma.sync m16n8k16 (fp32 accum), ldmatrix b16, cp.async,
// 3-stage ring, 2 CTAs/SM. Output type templated (half for kv/q stage).
// ---------------------------------------------------------------------------

#define M_ROWS 16384
#define DMODEL 1024
#define KV_COLS 2048

__device__ __half g_kvh [(size_t)M_ROWS * KV_COLS];
__device__ __half g_qh  [(size_t)M_ROWS * DMODEL];
__device__ __half g_xh  [(size_t)M_ROWS * DMODEL];
__device__ __half g_yh  [(size_t)M_ROWS * DMODEL];
__device__ __half g_valh[(size_t)M_ROWS * DMODEL];
__device__ __half g_wkvT[(size_t)KV_COLS * DMODEL];
__device__ __half g_wqT [(size_t)DMODEL * DMODEL];
__device__ __half g_woT [(size_t)DMODEL * DMODEL];

__device__ __forceinline__ uint32_t smem_u32(const void* p) {
    uint32_t a;
    asm("{ .reg .u64 t; cvta.to.shared.u64 t, %1; cvt.u32.u64 %0, t; }"
        : "=r"(a) : "l"(p));
    return a;
}

__device__ __forceinline__ void cp_async16(uint32_t saddr, const void* gaddr) {
    asm volatile("cp.async.cg.shared.global [%0], [%1], 16;"
                 :: "r"(saddr), "l"(gaddr));
}
#define CP_COMMIT() asm volatile("cp.async.commit_group;" ::: "memory")
#define CP_WAIT(n)  asm volatile("cp.async.wait_group %0;" :: "n"(n) : "memory")

__device__ __forceinline__ void ldsm_x4(uint32_t& r0, uint32_t& r1,
                                        uint32_t& r2, uint32_t& r3, uint32_t a) {
    asm volatile("ldmatrix.sync.aligned.m8n8.x4.shared.b16 {%0,%1,%2,%3}, [%4];"
                 : "=r"(r0), "=r"(r1), "=r"(r2), "=r"(r3) : "r"(a));
}

__device__ __forceinline__ void mma_f16(float* d, const uint32_t* a,
                                        uint32_t b0, uint32_t b1) {
    asm volatile(
        "mma.sync.aligned.m16n8k16.row.col.f32.f16.f16.f32 "
        "{%0,%1,%2,%3}, {%4,%5,%6,%7}, {%8,%9}, {%0,%1,%2,%3};"
        : "+f"(d[0]), "+f"(d[1]), "+f"(d[2]), "+f"(d[3])
        : "r"(a[0]), "r"(a[1]), "r"(a[2]), "r"(a[3]), "r"(b0), "r"(b1));
}

// ---------------------------------------------------------------------------
// GEMM: C[M,N](OutT) = Ah[M,K](fp16) @ BTh[N,K](fp16)^T + bias(fp32)
// 128x128 tile, BK=64, 3-stage cp.async ring, 8 warps x (64x32 warp tile)
// ---------------------------------------------------------------------------
#define BM 128
#define BN 128
#define BK 64
#define APH 72                              // halves per smem row (64 + 8 pad)
#define ROWB (APH * 2)                      // 144 B row stride
#define TILE_BYTES (128 * ROWB)             // 18432
#define STAGE_BYTES (2 * TILE_BYTES)        // 36864
#define NSTAGE 3
#define GEMM_SMEM (NSTAGE * STAGE_BYTES)    // 110592 B -> 2 CTAs/SM

template <typename OutT>
__global__ __launch_bounds__(256, 2) void gemm_f16_kernel(
    const __half* __restrict__ A, const __half* __restrict__ BT,
    const float* __restrict__ bias, OutT* __restrict__ C,
    int N, int K)
{
    extern __shared__ char smem[];
    const uint32_t sbase = smem_u32(smem);
    const int tid  = threadIdx.x;
    const int wid  = tid >> 5;
    const int lane = tid & 31;
    const int brow = blockIdx.y * BM;
    const int bcol = blockIdx.x * BN;

    const int wm = wid & 1;      // 2 m-groups of 64
    const int wn = wid >> 1;     // 4 n-groups of 32

    const int lr = lane & 7, lg = lane >> 3;
    const uint32_t frag_lane = (uint32_t)(((lg & 1) * 8 + lr) * ROWB + (lg >> 1) * 16);

    float acc[4][4][4];
#pragma unroll
    for (int i = 0; i < 4; i++)
#pragma unroll
        for (int j = 0; j < 4; j++)
#pragma unroll
            for (int f = 0; f < 4; f++) acc[i][j][f] = 0.f;

    const int NS = K / BK;   // 16

    auto issue = [&](int s, int slot) {
        const int k0 = s * BK;
        const uint32_t sa = sbase + (uint32_t)(slot * STAGE_BYTES);
        const uint32_t sb = sa + TILE_BYTES;
#pragma unroll
        for (int i = 0; i < 4; i++) {
            const int c = tid + i * 256;
            const int row = c >> 3, kc = c & 7;
            cp_async16(sa + (uint32_t)(row * ROWB + kc * 16),
                       A + (size_t)(brow + row) * K + k0 + kc * 8);
        }
#pragma unroll
        for (int i = 0; i < 4; i++) {
            const int c = tid + i * 256;
            const int row = c >> 3, kc = c & 7;
            cp_async16(sb + (uint32_t)(row * ROWB + kc * 16),
                       BT + (size_t)(bcol + row) * K + k0 + kc * 8);
        }
    };

    issue(0, 0); CP_COMMIT();
    issue(1, 1); CP_COMMIT();

    int slot = 0, nslot = 2;
    for (int s = 0; s < NS; s++) {
        CP_WAIT(1);
        __syncthreads();
        if (s + 2 < NS) issue(s + 2, nslot);
        CP_COMMIT();

        const uint32_t sa = sbase + (uint32_t)(slot * STAGE_BYTES);
        const uint32_t sb = sa + TILE_BYTES;
        const uint32_t aw = sa + frag_lane + (uint32_t)(wm * 64 * ROWB);
        const uint32_t bw = sb + frag_lane + (uint32_t)(wn * 32 * ROWB);

#pragma unroll
        for (int kk = 0; kk < 4; kk++) {           // 4 k16-steps (32 B each)
            uint32_t af[4][4];
#pragma unroll
            for (int mi = 0; mi < 4; mi++)
                ldsm_x4(af[mi][0], af[mi][1], af[mi][2], af[mi][3],
                        aw + (uint32_t)(mi * 16 * ROWB + kk * 32));
            uint32_t bf[2][4];
#pragma unroll
            for (int ni = 0; ni < 2; ni++)
                ldsm_x4(bf[ni][0], bf[ni][1], bf[ni][2], bf[ni][3],
                        bw + (uint32_t)(ni * 16 * ROWB + kk * 32));
#pragma unroll
            for (int mi = 0; mi < 4; mi++)
#pragma unroll
                for (int nj = 0; nj < 4; nj++)
                    mma_f16(acc[mi][nj], af[mi],
                            bf[nj >> 1][nj & 1], bf[nj >> 1][(nj & 1) + 2]);
        }

        slot = (slot == NSTAGE - 1) ? 0 : slot + 1;
        nslot = (nslot == NSTAGE - 1) ? 0 : nslot + 1;
    }

    // epilogue: + bias
    const int lr4 = lane >> 2;
    const int lc2 = (lane & 3) * 2;
#pragma unroll
    for (int mi = 0; mi < 4; mi++) {
        const int r0 = brow + wm * 64 + mi * 16 + lr4;
#pragma unroll
        for (int nj = 0; nj < 4; nj++) {
            const int c = bcol + wn * 32 + nj * 8 + lc2;
            const float bx = bias[c], by = bias[c + 1];
            if constexpr (sizeof(OutT) == 4) {
                float2 v0 = {acc[mi][nj][0] + bx, acc[mi][nj][1] + by};
                float2 v1 = {acc[mi][nj][2] + bx, acc[mi][nj][3] + by};
                *reinterpret_cast<float2*>((float*)C + (size_t)r0 * N + c) = v0;
                *reinterpret_cast<float2*>((float*)C + (size_t)(r0 + 8) * N + c) = v1;
            } else {
                __half2 v0 = __floats2half2_rn(acc[mi][nj][0] + bx, acc[mi][nj][1] + by);
                __half2 v1 = __floats2half2_rn(acc[mi][nj][2] + bx, acc[mi][nj][3] + by);
                *reinterpret_cast<__half2*>((__half*)C + (size_t)r0 * N + c) = v0;
                *reinterpret_cast<__half2*>((__half*)C + (size_t)(r0 + 8) * N + c) = v1;
            }
        }
    }
}

// ---------------------------------------------------------------------------
// fp32 -> fp16 bulk convert (8 elems/thread)
// ---------------------------------------------------------------------------
__global__ void cvt_f16_kernel(const float* __restrict__ in, __half* __restrict__ out)
{
    const size_t i = (size_t)(blockIdx.x * blockDim.x + threadIdx.x) * 8;
    float4 a = *reinterpret_cast<const float4*>(in + i);
    float4 b = *reinterpret_cast<const float4*>(in + i + 4);
    __half2 h[4];
    h[0] = __floats2half2_rn(a.x, a.y);
    h[1] = __floats2half2_rn(a.z, a.w);
    h[2] = __floats2half2_rn(b.x, b.y);
    h[3] = __floats2half2_rn(b.z, b.w);
    *reinterpret_cast<uint4*>(out + i) = *reinterpret_cast<uint4*>(h);
}

// ---------------------------------------------------------------------------
// Weight transpose + fp16 convert: out[N,K](half) = in[K,N](fp32)
// ---------------------------------------------------------------------------
__global__ void transpose_h_kernel(const float* __restrict__ in, __half* __restrict__ out,
                                   int R, int Ccols)
{
    __shared__ float t[32][33];
    const int c = blockIdx.x * 32 + threadIdx.x;
    const int r = blockIdx.y * 32 + threadIdx.y;
#pragma unroll
    for (int i = 0; i < 32; i += 8)
        t[threadIdx.y + i][threadIdx.x] = in[(size_t)(r + i) * Ccols + c];
    __syncthreads();
    const int oc   = blockIdx.y * 32 + threadIdx.x;
    const int orow = blockIdx.x * 32 + threadIdx.y;
#pragma unroll
    for (int i = 0; i < 32; i += 8)
        out[(size_t)(orow + i) * R + oc] = __float2half_rn(t[threadIdx.x][threadIdx.y + i]);
}

// ---------------------------------------------------------------------------
// Per-position head-axis attention: fp16 in (q, kv), fp32 math, fp16 val out.
// ---------------------------------------------------------------------------
#define KV_PAD 132

__global__ __launch_bounds__(256) void attn_kernel(
    const __half* __restrict__ qbuf, const __half* __restrict__ kvbuf,
    __half* __restrict__ valbuf)
{
    __shared__ float sq[1024];
    __shared__ float skv[16 * KV_PAD];
    __shared__ float sP[16][16];

    const int p   = blockIdx.x;
    const int tid = threadIdx.x;

    // q: 1024 halves; 4 per thread
    {
        const uint2 raw = *reinterpret_cast<const uint2*>(
            qbuf + (size_t)p * 1024 + tid * 4);
        const __half2 h0 = *reinterpret_cast<const __half2*>(&raw.x);
        const __half2 h1 = *reinterpret_cast<const __half2*>(&raw.y);
        float2 f0 = __half22float2(h0), f1 = __half22float2(h1);
        *reinterpret_cast<float4*>(&sq[tid * 4]) =
            make_float4(f0.x, f0.y, f1.x, f1.y);
    }
    // kv: 2048 halves; 8 per thread -> padded [16][KV_PAD]
    {
        const uint4 raw = *reinterpret_cast<const uint4*>(
            kvbuf + (size_t)p * 2048 + tid * 8);
        const __half2* hp = reinterpret_cast<const __half2*>(&raw);
        const int h = tid >> 4;            // 16 threads per kv row (128 halves)
        const int c = (tid & 15) * 8;
        float* dst = &skv[h * KV_PAD + c];
        float2 f0 = __half22float2(hp[0]), f1 = __half22float2(hp[1]);
        float2 f2 = __half22float2(hp[2]), f3 = __half22float2(hp[3]);
        *reinterpret_cast<float4*>(dst)     = make_float4(f0.x, f0.y, f1.x, f1.y);
        *reinterpret_cast<float4*>(dst + 4) = make_float4(f2.x, f2.y, f3.x, f3.y);
    }
    __syncthreads();

    {
        const int h = tid >> 4, g = tid & 15;
        const float* qr = sq  + h * 64;
        const float* kr = skv + g * KV_PAD;
        float s = 0.f;
#pragma unroll
        for (int d = 0; d < 64; d++) s += qr[d] * kr[d];
        sP[h][g] = s * 0.125f;
    }
    __syncthreads();

    if (tid < 16) {
        float m = -1e30f;
#pragma unroll
        for (int g = 0; g < 16; g++) m = fmaxf(m, sP[tid][g]);
        float e[16], sum = 0.f;
#pragma unroll
        for (int g = 0; g < 16; g++) { e[g] = __expf(sP[tid][g] - m); sum += e[g]; }
        const float inv = 1.f / sum;
#pragma unroll
        for (int g = 0; g < 16; g++) sP[tid][g] = e[g] * inv;
    }
    __syncthreads();

    {
        const int h  = tid >> 4;
        const int d0 = (tid & 15) * 4;
        float4 o = {0.f, 0.f, 0.f, 0.f};
#pragma unroll
        for (int g = 0; g < 16; g++) {
            const float pv = sP[h][g];
            const float4 vv = *reinterpret_cast<const float4*>(&skv[g * KV_PAD + 64 + d0]);
            o.x += pv * vv.x; o.y += pv * vv.y;
            o.z += pv * vv.z; o.w += pv * vv.w;
        }
        __half2 h01 = __floats2half2_rn(o.x, o.y);
        __half2 h23 = __floats2half2_rn(o.z, o.w);
        uint2 pk = {*reinterpret_cast<uint32_t*>(&h01), *reinterpret_cast<uint32_t*>(&h23)};
        *reinterpret_cast<uint2*>(valbuf + (size_t)p * 1024 + h * 64 + d0) = pk;
    }
}

// ---------------------------------------------------------------------------

extern "C" void kernel_launch(void* const* d_in, const int* in_sizes, int n_in,
                              void* d_out, int out_size)
{
    const float* x   = (const float*)d_in[0];
    const float* y   = (const float*)d_in[1];
    const float* Wkv = (const float*)d_in[2];
    const float* bkv = (const float*)d_in[3];
    const float* Wq  = (const float*)d_in[4];
    const float* bq  = (const float*)d_in[5];
    const float* Wo  = (const float*)d_in[6];
    const float* bo  = (const float*)d_in[7];
    float* out = (float*)d_out;

    __half *kvh_p, *qh_p, *xh_p, *yh_p, *valh_p, *wkvT_p, *wqT_p, *woT_p;
    cudaGetSymbolAddress((void**)&kvh_p,  g_kvh);
    cudaGetSymbolAddress((void**)&qh_p,   g_qh);
    cudaGetSymbolAddress((void**)&xh_p,   g_xh);
    cudaGetSymbolAddress((void**)&yh_p,   g_yh);
    cudaGetSymbolAddress((void**)&valh_p, g_valh);
    cudaGetSymbolAddress((void**)&wkvT_p, g_wkvT);
    cudaGetSymbolAddress((void**)&wqT_p,  g_wqT);
    cudaGetSymbolAddress((void**)&woT_p,  g_woT);

    cudaFuncSetAttribute(gemm_f16_kernel<float>,
                         cudaFuncAttributeMaxDynamicSharedMemorySize, GEMM_SMEM);
    cudaFuncSetAttribute(gemm_f16_kernel<__half>,
                         cudaFuncAttributeMaxDynamicSharedMemorySize, GEMM_SMEM);

    // input converts + weight transposes
    const int cvt_blocks = (M_ROWS * DMODEL) / (256 * 8);
    cvt_f16_kernel<<<cvt_blocks, 256>>>(x, xh_p);
    cvt_f16_kernel<<<cvt_blocks, 256>>>(y, yh_p);
    transpose_h_kernel<<<dim3(KV_COLS / 32, DMODEL / 32), dim3(32, 8)>>>(Wkv, wkvT_p, DMODEL, KV_COLS);
    transpose_h_kernel<<<dim3(DMODEL / 32, DMODEL / 32), dim3(32, 8)>>>(Wq, wqT_p, DMODEL, DMODEL);
    transpose_h_kernel<<<dim3(DMODEL / 32, DMODEL / 32), dim3(32, 8)>>>(Wo, woT_p, DMODEL, DMODEL);

    // GEMM1: kv = x @ Wkv + bkv  (fp16 out)
    gemm_f16_kernel<__half><<<dim3(KV_COLS / BN, M_ROWS / BM), 256, GEMM_SMEM>>>(
        xh_p, wkvT_p, bkv, kvh_p, KV_COLS, DMODEL);
    // GEMM2: q = y @ Wq + bq  (fp16 out)
    gemm_f16_kernel<__half><<<dim3(DMODEL / BN, M_ROWS / BM), 256, GEMM_SMEM>>>(
        yh_p, wqT_p, bq, qh_p, DMODEL, DMODEL);
    // attention (fp16 in/out, fp32 math)
    attn_kernel<<<M_ROWS, 256>>>(qh_p, kvh_p, valh_p);
    // GEMM3: out = val @ Wo + bo  (fp32 out)
    gemm_f16_kernel<float><<<dim3(DMODEL / BN, M_ROWS / BM), 256, GEMM_SMEM>>>(
        valh_p, woT_p, bo, out, DMODEL, DMODEL);
}

// round 8
// speedup vs baseline: 4.9569x; 1.0208x over previous
#include <cuda_runtime.h>
#include <cuda_fp16.h>
#include <cstdint>

// ---------------------------------------------------------------------------
// MultiHead_CrossAttention: B=4, L=4096, D=1024, H=16, hd=64
//   kv  = x @ Wkv + bkv      [16384, 2048]  (fp16 staged)
//   q   = y @ Wq  + bq       [16384, 1024]  (fp16 staged)
//   per-position head-axis attention (16x16 softmax, fp32 math)
//   out = val @ Wo + bo      [16384, 1024]  (fp32)
// GEMMs: fp16 mma.sync m16n8k16 (fp32 accum), ldmatrix, cp.async, 3-stage
// ring, 2 CTAs/SM, warp-staggered kk order (SMSP pipe de-bursting).
// ---------------------------------------------------------------------------

#define M_ROWS 16384
#define DMODEL 1024
#define KV_COLS 2048

__device__ __half g_kvh [(size_t)M_ROWS * KV_COLS];
__device__ __half g_qh  [(size_t)M_ROWS * DMODEL];
__device__ __half g_xh  [(size_t)M_ROWS * DMODEL];
__device__ __half g_yh  [(size_t)M_ROWS * DMODEL];
__device__ __half g_valh[(size_t)M_ROWS * DMODEL];
__device__ __half g_wkvT[(size_t)KV_COLS * DMODEL];
__device__ __half g_wqT [(size_t)DMODEL * DMODEL];
__device__ __half g_woT [(size_t)DMODEL * DMODEL];

__device__ __forceinline__ uint32_t smem_u32(const void* p) {
    uint32_t a;
    asm("{ .reg .u64 t; cvta.to.shared.u64 t, %1; cvt.u32.u64 %0, t; }"
        : "=r"(a) : "l"(p));
    return a;
}

__device__ __forceinline__ void cp_async16(uint32_t saddr, const void* gaddr) {
    asm volatile("cp.async.cg.shared.global [%0], [%1], 16;"
                 :: "r"(saddr), "l"(gaddr));
}
#define CP_COMMIT() asm volatile("cp.async.commit_group;" ::: "memory")
#define CP_WAIT(n)  asm volatile("cp.async.wait_group %0;" :: "n"(n) : "memory")

__device__ __forceinline__ void ldsm_x4(uint32_t& r0, uint32_t& r1,
                                        uint32_t& r2, uint32_t& r3, uint32_t a) {
    asm volatile("ldmatrix.sync.aligned.m8n8.x4.shared.b16 {%0,%1,%2,%3}, [%4];"
                 : "=r"(r0), "=r"(r1), "=r"(r2), "=r"(r3) : "r"(a));
}

__device__ __forceinline__ void mma_f16(float* d, const uint32_t* a,
                                        uint32_t b0, uint32_t b1) {
    asm volatile(
        "mma.sync.aligned.m16n8k16.row.col.f32.f16.f16.f32 "
        "{%0,%1,%2,%3}, {%4,%5,%6,%7}, {%8,%9}, {%0,%1,%2,%3};"
        : "+f"(d[0]), "+f"(d[1]), "+f"(d[2]), "+f"(d[3])
        : "r"(a[0]), "r"(a[1]), "r"(a[2]), "r"(a[3]), "r"(b0), "r"(b1));
}

// ---------------------------------------------------------------------------
// GEMM: C[M,N](OutT) = Ah[M,K](fp16) @ BTh[N,K](fp16)^T + bias(fp32)
// 128x128 tile, BK=64, 3-stage cp.async ring, 8 warps x (64x32 warp tile)
// ---------------------------------------------------------------------------
#define BM 128
#define BN 128
#define BK 64
#define APH 72                              // halves per smem row (64 + 8 pad)
#define ROWB (APH * 2)                      // 144 B row stride
#define TILE_BYTES (128 * ROWB)             // 18432
#define STAGE_BYTES (2 * TILE_BYTES)        // 36864
#define NSTAGE 3
#define GEMM_SMEM (NSTAGE * STAGE_BYTES)    // 110592 B -> 2 CTAs/SM

template <typename OutT>
__global__ __launch_bounds__(256, 2) void gemm_f16_kernel(
    const __half* __restrict__ A, const __half* __restrict__ BT,
    const float* __restrict__ bias, OutT* __restrict__ C,
    int N, int K)
{
    extern __shared__ char smem[];
    const uint32_t sbase = smem_u32(smem);
    const int tid  = threadIdx.x;
    const int wid  = tid >> 5;
    const int lane = tid & 31;
    const int brow = blockIdx.y * BM;
    const int bcol = blockIdx.x * BN;

    const int wm = wid & 1;      // 2 m-groups of 64
    const int wn = wid >> 1;     // 4 n-groups of 32

    // kk-phase stagger: the two warps sharing an SMSP (wid, wid+4) run
    // opposite k16-chunk orders -> tensor-pipe issue is de-bursted.
    const uint32_t koff = ((wid >> 2) & 1) * 64;   // XOR on kk*32 (bit 6)

    const int lr = lane & 7, lg = lane >> 3;
    const uint32_t frag_lane = (uint32_t)(((lg & 1) * 8 + lr) * ROWB + (lg >> 1) * 16);

    float acc[4][4][4];
#pragma unroll
    for (int i = 0; i < 4; i++)
#pragma unroll
        for (int j = 0; j < 4; j++)
#pragma unroll
            for (int f = 0; f < 4; f++) acc[i][j][f] = 0.f;

    const int NS = K / BK;   // 16

    auto issue = [&](int s, int slot) {
        const int k0 = s * BK;
        const uint32_t sa = sbase + (uint32_t)(slot * STAGE_BYTES);
        const uint32_t sb = sa + TILE_BYTES;
#pragma unroll
        for (int i = 0; i < 4; i++) {
            const int c = tid + i * 256;
            const int row = c >> 3, kc = c & 7;
            cp_async16(sa + (uint32_t)(row * ROWB + kc * 16),
                       A + (size_t)(brow + row) * K + k0 + kc * 8);
        }
#pragma unroll
        for (int i = 0; i < 4; i++) {
            const int c = tid + i * 256;
            const int row = c >> 3, kc = c & 7;
            cp_async16(sb + (uint32_t)(row * ROWB + kc * 16),
                       BT + (size_t)(bcol + row) * K + k0 + kc * 8);
        }
    };

    issue(0, 0); CP_COMMIT();
    issue(1, 1); CP_COMMIT();

    int slot = 0, nslot = 2;
    for (int s = 0; s < NS; s++) {
        CP_WAIT(1);
        __syncthreads();
        if (s + 2 < NS) issue(s + 2, nslot);
        CP_COMMIT();

        const uint32_t sa = sbase + (uint32_t)(slot * STAGE_BYTES);
        const uint32_t sb = sa + TILE_BYTES;
        const uint32_t aw = sa + frag_lane + (uint32_t)(wm * 64 * ROWB);
        const uint32_t bw = sb + frag_lane + (uint32_t)(wn * 32 * ROWB);

#pragma unroll
        for (int kk = 0; kk < 4; kk++) {           // 4 k16-steps, warp-staggered
            const uint32_t ko = (uint32_t)(kk * 32) ^ koff;
            uint32_t af[4][4];
#pragma unroll
            for (int mi = 0; mi < 4; mi++)
                ldsm_x4(af[mi][0], af[mi][1], af[mi][2], af[mi][3],
                        aw + (uint32_t)(mi * 16 * ROWB) + ko);
            uint32_t bf[2][4];
#pragma unroll
            for (int ni = 0; ni < 2; ni++)
                ldsm_x4(bf[ni][0], bf[ni][1], bf[ni][2], bf[ni][3],
                        bw + (uint32_t)(ni * 16 * ROWB) + ko);
#pragma unroll
            for (int mi = 0; mi < 4; mi++)
#pragma unroll
                for (int nj = 0; nj < 4; nj++)
                    mma_f16(acc[mi][nj], af[mi],
                            bf[nj >> 1][nj & 1], bf[nj >> 1][(nj & 1) + 2]);
        }

        slot = (slot == NSTAGE - 1) ? 0 : slot + 1;
        nslot = (nslot == NSTAGE - 1) ? 0 : nslot + 1;
    }

    // epilogue: + bias
    const int lr4 = lane >> 2;
    const int lc2 = (lane & 3) * 2;
#pragma unroll
    for (int mi = 0; mi < 4; mi++) {
        const int r0 = brow + wm * 64 + mi * 16 + lr4;
#pragma unroll
        for (int nj = 0; nj < 4; nj++) {
            const int c = bcol + wn * 32 + nj * 8 + lc2;
            const float bx = bias[c], by = bias[c + 1];
            if constexpr (sizeof(OutT) == 4) {
                float2 v0 = {acc[mi][nj][0] + bx, acc[mi][nj][1] + by};
                float2 v1 = {acc[mi][nj][2] + bx, acc[mi][nj][3] + by};
                *reinterpret_cast<float2*>((float*)C + (size_t)r0 * N + c) = v0;
                *reinterpret_cast<float2*>((float*)C + (size_t)(r0 + 8) * N + c) = v1;
            } else {
                __half2 v0 = __floats2half2_rn(acc[mi][nj][0] + bx, acc[mi][nj][1] + by);
                __half2 v1 = __floats2half2_rn(acc[mi][nj][2] + bx, acc[mi][nj][3] + by);
                *reinterpret_cast<__half2*>((__half*)C + (size_t)r0 * N + c) = v0;
                *reinterpret_cast<__half2*>((__half*)C + (size_t)(r0 + 8) * N + c) = v1;
            }
        }
    }
}

// ---------------------------------------------------------------------------
// fp32 -> fp16 bulk convert, x and y in ONE launch (blockIdx.y selects tensor)
// ---------------------------------------------------------------------------
__global__ void cvt_f16_dual_kernel(const float* __restrict__ x, __half* __restrict__ xh,
                                    const float* __restrict__ y, __half* __restrict__ yh)
{
    const float* in  = blockIdx.y ? y  : x;
    __half*      out = blockIdx.y ? yh : xh;
    const size_t i = (size_t)(blockIdx.x * blockDim.x + threadIdx.x) * 8;
    float4 a = *reinterpret_cast<const float4*>(in + i);
    float4 b = *reinterpret_cast<const float4*>(in + i + 4);
    __half2 h[4];
    h[0] = __floats2half2_rn(a.x, a.y);
    h[1] = __floats2half2_rn(a.z, a.w);
    h[2] = __floats2half2_rn(b.x, b.y);
    h[3] = __floats2half2_rn(b.z, b.w);
    *reinterpret_cast<uint4*>(out + i) = *reinterpret_cast<uint4*>(h);
}

// ---------------------------------------------------------------------------
// Batched weight transpose + fp16 convert: all 3 weights in one launch.
// z=0: Wkv [1024,2048], z=1: Wq [1024,1024], z=2: Wo [1024,1024]
// ---------------------------------------------------------------------------
__global__ void transpose3_kernel(const float* __restrict__ Wkv, __half* __restrict__ WkvT,
                                  const float* __restrict__ Wq,  __half* __restrict__ WqT,
                                  const float* __restrict__ Wo,  __half* __restrict__ WoT)
{
    const int z = blockIdx.z;
    const float* in; __half* out; int Ccols;
    if (z == 0)      { in = Wkv; out = WkvT; Ccols = KV_COLS; }
    else if (z == 1) { in = Wq;  out = WqT;  Ccols = DMODEL;  }
    else             { in = Wo;  out = WoT;  Ccols = DMODEL;  }
    if (blockIdx.x * 32 >= Ccols) return;
    const int R = DMODEL;

    __shared__ float t[32][33];
    const int c = blockIdx.x * 32 + threadIdx.x;
    const int r = blockIdx.y * 32 + threadIdx.y;
#pragma unroll
    for (int i = 0; i < 32; i += 8)
        t[threadIdx.y + i][threadIdx.x] = in[(size_t)(r + i) * Ccols + c];
    __syncthreads();
    const int oc   = blockIdx.y * 32 + threadIdx.x;
    const int orow = blockIdx.x * 32 + threadIdx.y;
#pragma unroll
    for (int i = 0; i < 32; i += 8)
        out[(size_t)(orow + i) * R + oc] = __float2half_rn(t[threadIdx.x][threadIdx.y + i]);
}

// ---------------------------------------------------------------------------
// Per-position head-axis attention: fp16 in (q, kv), fp32 math, fp16 val out.
// ---------------------------------------------------------------------------
#define KV_PAD 132

__global__ __launch_bounds__(256) void attn_kernel(
    const __half* __restrict__ qbuf, const __half* __restrict__ kvbuf,
    __half* __restrict__ valbuf)
{
    __shared__ float sq[1024];
    __shared__ float skv[16 * KV_PAD];
    __shared__ float sP[16][16];

    const int p   = blockIdx.x;
    const int tid = threadIdx.x;

    {
        const uint2 raw = *reinterpret_cast<const uint2*>(
            qbuf + (size_t)p * 1024 + tid * 4);
        const __half2 h0 = *reinterpret_cast<const __half2*>(&raw.x);
        const __half2 h1 = *reinterpret_cast<const __half2*>(&raw.y);
        float2 f0 = __half22float2(h0), f1 = __half22float2(h1);
        *reinterpret_cast<float4*>(&sq[tid * 4]) =
            make_float4(f0.x, f0.y, f1.x, f1.y);
    }
    {
        const uint4 raw = *reinterpret_cast<const uint4*>(
            kvbuf + (size_t)p * 2048 + tid * 8);
        const __half2* hp = reinterpret_cast<const __half2*>(&raw);
        const int h = tid >> 4;
        const int c = (tid & 15) * 8;
        float* dst = &skv[h * KV_PAD + c];
        float2 f0 = __half22float2(hp[0]), f1 = __half22float2(hp[1]);
        float2 f2 = __half22float2(hp[2]), f3 = __half22float2(hp[3]);
        *reinterpret_cast<float4*>(dst)     = make_float4(f0.x, f0.y, f1.x, f1.y);
        *reinterpret_cast<float4*>(dst + 4) = make_float4(f2.x, f2.y, f3.x, f3.y);
    }
    __syncthreads();

    {
        const int h = tid >> 4, g = tid & 15;
        const float* qr = sq  + h * 64;
        const float* kr = skv + g * KV_PAD;
        float s = 0.f;
#pragma unroll
        for (int d = 0; d < 64; d++) s += qr[d] * kr[d];
        sP[h][g] = s * 0.125f;
    }
    __syncthreads();

    if (tid < 16) {
        float m = -1e30f;
#pragma unroll
        for (int g = 0; g < 16; g++) m = fmaxf(m, sP[tid][g]);
        float e[16], sum = 0.f;
#pragma unroll
        for (int g = 0; g < 16; g++) { e[g] = __expf(sP[tid][g] - m); sum += e[g]; }
        const float inv = 1.f / sum;
#pragma unroll
        for (int g = 0; g < 16; g++) sP[tid][g] = e[g] * inv;
    }
    __syncthreads();

    {
        const int h  = tid >> 4;
        const int d0 = (tid & 15) * 4;
        float4 o = {0.f, 0.f, 0.f, 0.f};
#pragma unroll
        for (int g = 0; g < 16; g++) {
            const float pv = sP[h][g];
            const float4 vv = *reinterpret_cast<const float4*>(&skv[g * KV_PAD + 64 + d0]);
            o.x += pv * vv.x; o.y += pv * vv.y;
            o.z += pv * vv.z; o.w += pv * vv.w;
        }
        __half2 h01 = __floats2half2_rn(o.x, o.y);
        __half2 h23 = __floats2half2_rn(o.z, o.w);
        uint2 pk = {*reinterpret_cast<uint32_t*>(&h01), *reinterpret_cast<uint32_t*>(&h23)};
        *reinterpret_cast<uint2*>(valbuf + (size_t)p * 1024 + h * 64 + d0) = pk;
    }
}

// ---------------------------------------------------------------------------

extern "C" void kernel_launch(void* const* d_in, const int* in_sizes, int n_in,
                              void* d_out, int out_size)
{
    const float* x   = (const float*)d_in[0];
    const float* y   = (const float*)d_in[1];
    const float* Wkv = (const float*)d_in[2];
    const float* bkv = (const float*)d_in[3];
    const float* Wq  = (const float*)d_in[4];
    const float* bq  = (const float*)d_in[5];
    const float* Wo  = (const float*)d_in[6];
    const float* bo  = (const float*)d_in[7];
    float* out = (float*)d_out;

    __half *kvh_p, *qh_p, *xh_p, *yh_p, *valh_p, *wkvT_p, *wqT_p, *woT_p;
    cudaGetSymbolAddress((void**)&kvh_p,  g_kvh);
    cudaGetSymbolAddress((void**)&qh_p,   g_qh);
    cudaGetSymbolAddress((void**)&xh_p,   g_xh);
    cudaGetSymbolAddress((void**)&yh_p,   g_yh);
    cudaGetSymbolAddress((void**)&valh_p, g_valh);
    cudaGetSymbolAddress((void**)&wkvT_p, g_wkvT);
    cudaGetSymbolAddress((void**)&wqT_p,  g_wqT);
    cudaGetSymbolAddress((void**)&woT_p,  g_woT);

    cudaFuncSetAttribute(gemm_f16_kernel<float>,
                         cudaFuncAttributeMaxDynamicSharedMemorySize, GEMM_SMEM);
    cudaFuncSetAttribute(gemm_f16_kernel<__half>,
                         cudaFuncAttributeMaxDynamicSharedMemorySize, GEMM_SMEM);

    // input converts (1 launch) + weight transposes (1 launch)
    const int cvt_blocks = (M_ROWS * DMODEL) / (256 * 8);
    cvt_f16_dual_kernel<<<dim3(cvt_blocks, 2), 256>>>(x, xh_p, y, yh_p);
    transpose3_kernel<<<dim3(KV_COLS / 32, DMODEL / 32, 3), dim3(32, 8)>>>(
        Wkv, wkvT_p, Wq, wqT_p, Wo, woT_p);

    // GEMM1: kv = x @ Wkv + bkv  (fp16 out)
    gemm_f16_kernel<__half><<<dim3(KV_COLS / BN, M_ROWS / BM), 256, GEMM_SMEM>>>(
        xh_p, wkvT_p, bkv, kvh_p, KV_COLS, DMODEL);
    // GEMM2: q = y @ Wq + bq  (fp16 out)
    gemm_f16_kernel<__half><<<dim3(DMODEL / BN, M_ROWS / BM), 256, GEMM_SMEM>>>(
        yh_p, wqT_p, bq, qh_p, DMODEL, DMODEL);
    // attention (fp16 in/out, fp32 math)
    attn_kernel<<<M_ROWS, 256>>>(qh_p, kvh_p, valh_p);
    // GEMM3: out = val @ Wo + bo  (fp32 out)
    gemm_f16_kernel<float><<<dim3(DMODEL / BN, M_ROWS / BM), 256, GEMM_SMEM>>>(
        valh_p, woT_p, bo, out, DMODEL, DMODEL);
}